// round 1
// baseline (speedup 1.0000x reference)
#include <cuda_runtime.h>

#define B_ 8192
#define T_ 128
#define DT_ 0.01f
#define WARPS 8
#define THREADS 256
#define ROWS_PER_BLOCK 16
#define NBLK (B_ / ROWS_PER_BLOCK)

// shared memory layout (float offsets)
#define OFF_W1   0       // [18][512]
#define OFF_WEN2 9216    // [256]
#define OFF_WD2T 9472    // [6][256] (transposed Wd2)
#define OFF_CS   11008   // [8 warps][512][2 rows]
#define SMEM_FLOATS 19200
#define SMEM_BYTES (SMEM_FLOATS * 4)

__global__ void __launch_bounds__(THREADS, 2) visco_kernel(
    const float* __restrict__ e_,   const float* __restrict__ ed_,
    const float* __restrict__ E_,   const float* __restrict__ nu_,
    const float* __restrict__ We,   const float* __restrict__ be,
    const float* __restrict__ Wn,   const float* __restrict__ bn,
    const float* __restrict__ Wen1, const float* __restrict__ ben1,
    const float* __restrict__ Wen2, const float* __restrict__ ben2,
    const float* __restrict__ Wd1,  const float* __restrict__ bd1,
    const float* __restrict__ Wd2,  const float* __restrict__ bd2,
    float* __restrict__ out)
{
    extern __shared__ float sm[];
    float* W1s   = sm + OFF_W1;
    float* Wen2s = sm + OFF_WEN2;
    float* Wd2t  = sm + OFF_WD2T;
    float* cs    = sm + OFF_CS;

    const int tid  = threadIdx.x;
    const int lane = tid & 31;
    const int warp = tid >> 5;

    // ---- cooperative smem fill ----
    // Combined layer-1 weights for the 18 dynamic inputs (e6, edot6, xi6):
    // h<256 -> Wen1 (energy MLP), h>=256 -> Wd1 (kinetics MLP)
    for (int i = tid; i < 18 * 512; i += THREADS) {
        int k = i >> 9, h = i & 511;
        W1s[i] = (h < 256) ? Wen1[k * 256 + h] : Wd1[k * 256 + (h - 256)];
    }
    for (int i = tid; i < 256; i += THREADS) Wen2s[i] = Wen2[i];
    for (int i = tid; i < 6 * 256; i += THREADS) {
        int j = i >> 8, h = i & 255;
        Wd2t[i] = Wd2[h * 6 + j];   // transpose -> conflict-free float4 reads
    }

    const int gw   = blockIdx.x * WARPS + warp;
    const int rowA = gw * 2, rowB = gw * 2 + 1;

    // ---- precompute per-row constant part: c[h] = b1[h] + mf(32) @ W1[18:50][h] ----
    {
        const float EA = E_[rowA], nuA = nu_[rowA];
        const float EB = E_[rowB], nuB = nu_[rowB];
        #pragma unroll
        for (int q = 0; q < 4; q++) {
            const int h0 = 4 * lane + 128 * q;   // whole float4 lies in one half
            const float* bsrc = (h0 < 256) ? (ben1 + h0) : (bd1 + h0 - 256);
            float cA0 = bsrc[0], cA1 = bsrc[1], cA2 = bsrc[2], cA3 = bsrc[3];
            float cB0 = cA0, cB1 = cA1, cB2 = cA2, cB3 = cA3;
            const float* Wbase = (h0 < 256) ? (Wen1 + 18 * 256 + h0)
                                            : (Wd1  + 18 * 256 + h0 - 256);
            for (int k = 0; k < 32; k++) {
                float mA, mB;
                if (k < 16) { float w = We[k], b = be[k];       mA = EA * w + b;  mB = EB * w + b; }
                else        { float w = Wn[k-16], b = bn[k-16]; mA = nuA * w + b; mB = nuB * w + b; }
                float4 w4 = *(const float4*)(Wbase + k * 256);
                cA0 = fmaf(mA, w4.x, cA0); cA1 = fmaf(mA, w4.y, cA1);
                cA2 = fmaf(mA, w4.z, cA2); cA3 = fmaf(mA, w4.w, cA3);
                cB0 = fmaf(mB, w4.x, cB0); cB1 = fmaf(mB, w4.y, cB1);
                cB2 = fmaf(mB, w4.z, cB2); cB3 = fmaf(mB, w4.w, cB3);
            }
            float* cdst = cs + warp * 1024 + h0 * 2;  // interleaved [h][row]
            cdst[0] = cA0; cdst[1] = cB0; cdst[2] = cA1; cdst[3] = cB1;
            cdst[4] = cA2; cdst[5] = cB2; cdst[6] = cA3; cdst[7] = cB3;
        }
    }
    __syncthreads();

    float bd2r[6], xiA[6], xiB[6];
    #pragma unroll
    for (int j = 0; j < 6; j++) { bd2r[j] = bd2[j]; xiA[j] = 0.f; xiB[j] = 0.f; }
    const float ben2r = ben2[0];

    // lane -> (row, input-dim) mapping for the per-step e/edot gather
    const int l2  = lane & 15;
    const int r_l = (lane < 16) ? rowA : rowB;
    const bool ldp = (l2 < 12);
    const float* lsrc = (l2 < 6) ? e_ : ed_;
    const int d_l = (l2 < 6) ? l2 : (l2 - 6);
    const int baseidx = r_l * T_ * 6 + d_l;

    const float* W1w   = W1s + 4 * lane;               // + k*512 + 128*q
    const float* csw   = cs + warp * 1024 + 8 * lane;  // + 256*q
    const float* wen2w = Wen2s + 4 * lane;
    const float* wd2w  = Wd2t + 4 * lane;

    for (int t = 0; t < T_; t++) {
        float ld = 0.f;
        if (ldp) ld = lsrc[baseidx + t * 6];

        // init accumulators from precomputed constant part
        float uA[16], uB[16];
        #pragma unroll
        for (int q = 0; q < 4; q++) {
            float4 c01 = *(const float4*)(csw + 256 * q);
            float4 c23 = *(const float4*)(csw + 256 * q + 4);
            uA[4*q+0] = c01.x; uB[4*q+0] = c01.y;
            uA[4*q+1] = c01.z; uB[4*q+1] = c01.w;
            uA[4*q+2] = c23.x; uB[4*q+2] = c23.y;
            uA[4*q+3] = c23.z; uB[4*q+3] = c23.w;
        }

        // layer 1: 18 dynamic inputs x 512 hidden (W1 smem loads shared by both rows)
        #pragma unroll
        for (int k = 0; k < 18; k++) {
            float xA, xB;
            if (k < 12) {
                xA = __shfl_sync(0xffffffffu, ld, k);
                xB = __shfl_sync(0xffffffffu, ld, 16 + k);
            } else { xA = xiA[k - 12]; xB = xiB[k - 12]; }
            #pragma unroll
            for (int q = 0; q < 4; q++) {
                float4 w = *(const float4*)(W1w + k * 512 + 128 * q);
                uA[4*q+0] = fmaf(xA, w.x, uA[4*q+0]);
                uA[4*q+1] = fmaf(xA, w.y, uA[4*q+1]);
                uA[4*q+2] = fmaf(xA, w.z, uA[4*q+2]);
                uA[4*q+3] = fmaf(xA, w.w, uA[4*q+3]);
                uB[4*q+0] = fmaf(xB, w.x, uB[4*q+0]);
                uB[4*q+1] = fmaf(xB, w.y, uB[4*q+1]);
                uB[4*q+2] = fmaf(xB, w.z, uB[4*q+2]);
                uB[4*q+3] = fmaf(xB, w.w, uB[4*q+3]);
            }
        }

        // relu
        #pragma unroll
        for (int i = 0; i < 16; i++) {
            uA[i] = fmaxf(uA[i], 0.f);
            uB[i] = fmaxf(uB[i], 0.f);
        }

        // layer 2a: stress head (energy half, q=0,1)
        float sA = 0.f, sB = 0.f;
        #pragma unroll
        for (int q = 0; q < 2; q++) {
            float4 w = *(const float4*)(wen2w + 128 * q);
            sA += uA[4*q]*w.x + uA[4*q+1]*w.y + uA[4*q+2]*w.z + uA[4*q+3]*w.w;
            sB += uB[4*q]*w.x + uB[4*q+1]*w.y + uB[4*q+2]*w.z + uB[4*q+3]*w.w;
        }

        // layer 2b: kinetics head (q=2,3), Wd2 transposed in smem
        float pA[6], pB[6];
        #pragma unroll
        for (int j = 0; j < 6; j++) {
            float a = 0.f, b = 0.f;
            #pragma unroll
            for (int q = 2; q < 4; q++) {
                float4 w = *(const float4*)(wd2w + j * 256 + 128 * (q - 2));
                a += uA[4*q]*w.x + uA[4*q+1]*w.y + uA[4*q+2]*w.z + uA[4*q+3]*w.w;
                b += uB[4*q]*w.x + uB[4*q+1]*w.y + uB[4*q+2]*w.z + uB[4*q+3]*w.w;
            }
            pA[j] = a; pB[j] = b;
        }

        // butterfly reductions (results land in all lanes)
        #pragma unroll
        for (int off = 16; off; off >>= 1) {
            sA += __shfl_xor_sync(0xffffffffu, sA, off);
            sB += __shfl_xor_sync(0xffffffffu, sB, off);
            #pragma unroll
            for (int j = 0; j < 6; j++) {
                pA[j] += __shfl_xor_sync(0xffffffffu, pA[j], off);
                pB[j] += __shfl_xor_sync(0xffffffffu, pB[j], off);
            }
        }

        // outputs: stress[b,t] and xi BEFORE update
        if (lane == 0) {
            out[rowA * T_ + t] = sA + ben2r;
            float* xo = out + B_ * T_ + (rowA * T_ + t) * 6;
            *(float2*)(xo)     = make_float2(xiA[0], xiA[1]);
            *(float2*)(xo + 2) = make_float2(xiA[2], xiA[3]);
            *(float2*)(xo + 4) = make_float2(xiA[4], xiA[5]);
        } else if (lane == 1) {
            out[rowB * T_ + t] = sB + ben2r;
            float* xo = out + B_ * T_ + (rowB * T_ + t) * 6;
            *(float2*)(xo)     = make_float2(xiB[0], xiB[1]);
            *(float2*)(xo + 2) = make_float2(xiB[2], xiB[3]);
            *(float2*)(xo + 4) = make_float2(xiB[4], xiB[5]);
        }

        // explicit Euler update
        #pragma unroll
        for (int j = 0; j < 6; j++) {
            xiA[j] = fmaf(DT_, pA[j] + bd2r[j], xiA[j]);
            xiB[j] = fmaf(DT_, pB[j] + bd2r[j], xiB[j]);
        }
    }
}

extern "C" void kernel_launch(void* const* d_in, const int* in_sizes, int n_in,
                              void* d_out, int out_size) {
    (void)in_sizes; (void)n_in; (void)out_size;
    cudaFuncSetAttribute(visco_kernel,
                         cudaFuncAttributeMaxDynamicSharedMemorySize, SMEM_BYTES);
    visco_kernel<<<NBLK, THREADS, SMEM_BYTES>>>(
        (const float*)d_in[0],  (const float*)d_in[1],
        (const float*)d_in[2],  (const float*)d_in[3],
        (const float*)d_in[4],  (const float*)d_in[5],
        (const float*)d_in[6],  (const float*)d_in[7],
        (const float*)d_in[8],  (const float*)d_in[9],
        (const float*)d_in[10], (const float*)d_in[11],
        (const float*)d_in[12], (const float*)d_in[13],
        (const float*)d_in[14], (const float*)d_in[15],
        (float*)d_out);
}

// round 2
// speedup vs baseline: 1.4227x; 1.4227x over previous
#include <cuda_runtime.h>

#define B_ 8192
#define T_ 128
#define DT_ 0.01f
#define WARPS 4
#define THREADS 128
#define ROWS_PER_BLOCK 16
#define NBLK (B_ / ROWS_PER_BLOCK)

// shared memory layout (float offsets)
#define OFF_W1   0       // [18][512]
#define OFF_WEN2 9216    // [256]
#define OFF_WD2T 9472    // [6][256] (transposed Wd2)
#define OFF_CS   11008   // [4 warps][q=4][r=4][lane=32][4]
#define SMEM_FLOATS (11008 + WARPS * 2048)
#define SMEM_BYTES (SMEM_FLOATS * 4)

typedef unsigned long long u64;

__device__ __forceinline__ u64 ffma2(u64 a, u64 b, u64 c) {
    u64 d; asm("fma.rn.f32x2 %0, %1, %2, %3;" : "=l"(d) : "l"(a), "l"(b), "l"(c));
    return d;
}
__device__ __forceinline__ u64 dup2(float x) {
    u64 d; asm("mov.b64 %0, {%1, %1};" : "=l"(d) : "f"(x));
    return d;
}
__device__ __forceinline__ float2 unpk(u64 a) {
    float2 r; asm("mov.b64 {%0, %1}, %2;" : "=f"(r.x), "=f"(r.y) : "l"(a));
    return r;
}
__device__ __forceinline__ u64 pk2(float x, float y) {
    u64 d; asm("mov.b64 %0, {%1, %2};" : "=l"(d) : "f"(x), "f"(y));
    return d;
}
__device__ __forceinline__ u64 relu2(u64 a) {
    float2 v = unpk(a);
    return pk2(fmaxf(v.x, 0.f), fmaxf(v.y, 0.f));
}

__global__ void __launch_bounds__(THREADS, 2) visco_kernel(
    const float* __restrict__ e_,   const float* __restrict__ ed_,
    const float* __restrict__ E_,   const float* __restrict__ nu_,
    const float* __restrict__ We,   const float* __restrict__ be,
    const float* __restrict__ Wn,   const float* __restrict__ bn,
    const float* __restrict__ Wen1, const float* __restrict__ ben1,
    const float* __restrict__ Wen2, const float* __restrict__ ben2,
    const float* __restrict__ Wd1,  const float* __restrict__ bd1,
    const float* __restrict__ Wd2,  const float* __restrict__ bd2,
    float* __restrict__ out)
{
    extern __shared__ float sm[];
    float* W1s   = sm + OFF_W1;
    float* Wen2s = sm + OFF_WEN2;
    float* Wd2t  = sm + OFF_WD2T;
    float* cs    = sm + OFF_CS;

    const int tid  = threadIdx.x;
    const int lane = tid & 31;
    const int warp = tid >> 5;

    // ---- cooperative smem fill ----
    // Combined layer-1 weights for the 18 dynamic inputs (e6, edot6, xi6):
    // h<256 -> Wen1 (energy MLP), h>=256 -> Wd1 (kinetics MLP)
    for (int i = tid; i < 18 * 512; i += THREADS) {
        int k = i >> 9, h = i & 511;
        W1s[i] = (h < 256) ? Wen1[k * 256 + h] : Wd1[k * 256 + (h - 256)];
    }
    for (int i = tid; i < 256; i += THREADS) Wen2s[i] = Wen2[i];
    for (int i = tid; i < 6 * 256; i += THREADS) {
        int j = i >> 8, h = i & 255;
        Wd2t[i] = Wd2[h * 6 + j];   // transpose -> conflict-free float4 reads
    }

    const int gw   = blockIdx.x * WARPS + warp;
    const int row0 = gw * 4;

    // ---- precompute per-row constant part: c[h] = b1[h] + mf(32) @ W1[18:50][h] ----
    {
        float Er[4], nur[4];
        #pragma unroll
        for (int r = 0; r < 4; r++) { Er[r] = E_[row0 + r]; nur[r] = nu_[row0 + r]; }
        #pragma unroll
        for (int q = 0; q < 4; q++) {
            const int h0 = 4 * lane + 128 * q;   // whole float4 lies in one half
            const float* bsrc  = (h0 < 256) ? (ben1 + h0) : (bd1 + h0 - 256);
            const float* Wbase = (h0 < 256) ? (Wen1 + 18 * 256 + h0)
                                            : (Wd1  + 18 * 256 + h0 - 256);
            float c[4][4];  // [el][row]
            #pragma unroll
            for (int el = 0; el < 4; el++) {
                float b = bsrc[el];
                #pragma unroll
                for (int r = 0; r < 4; r++) c[el][r] = b;
            }
            for (int k = 0; k < 32; k++) {
                float w, b;
                if (k < 16) { w = We[k];      b = be[k]; }
                else        { w = Wn[k - 16]; b = bn[k - 16]; }
                float4 w4 = *(const float4*)(Wbase + k * 256);
                #pragma unroll
                for (int r = 0; r < 4; r++) {
                    float m = fmaf((k < 16) ? Er[r] : nur[r], w, b);
                    c[0][r] = fmaf(m, w4.x, c[0][r]);
                    c[1][r] = fmaf(m, w4.y, c[1][r]);
                    c[2][r] = fmaf(m, w4.z, c[2][r]);
                    c[3][r] = fmaf(m, w4.w, c[3][r]);
                }
            }
            #pragma unroll
            for (int r = 0; r < 4; r++) {
                *(float4*)(cs + warp * 2048 + ((q * 4 + r) * 32 + lane) * 4)
                    = make_float4(c[0][r], c[1][r], c[2][r], c[3][r]);
            }
        }
    }
    __syncthreads();

    float bd2r[6], xi[4][6];
    #pragma unroll
    for (int j = 0; j < 6; j++) {
        bd2r[j] = bd2[j];
        #pragma unroll
        for (int r = 0; r < 4; r++) xi[r][j] = 0.f;
    }
    const float ben2r = ben2[0];

    // lane -> (rowpair, input-dim) mapping for the per-step e/edot gather
    const int l2  = lane & 15;
    const bool ldp = (l2 < 12);
    const float* lsrc = (l2 < 6) ? e_ : ed_;
    const int d_l = (l2 < 6) ? l2 : (l2 - 6);
    const int rA = row0 + ((lane < 16) ? 0 : 1);   // source rows for ld0
    const int rB = row0 + ((lane < 16) ? 2 : 3);   // source rows for ld1
    const int base0 = rA * T_ * 6 + d_l;
    const int base1 = rB * T_ * 6 + d_l;

    const float* W1w = W1s + 4 * lane;                 // + k*512 + 128*q
    const float* csw = cs + warp * 2048 + 4 * lane;    // + (q*4+r)*128

    // hoist layer-2 weights into registers (loop-invariant)
    ulonglong2 wen2r[2];
    #pragma unroll
    for (int q = 0; q < 2; q++)
        wen2r[q] = *(const ulonglong2*)(Wen2s + 4 * lane + 128 * q);
    ulonglong2 wd2r[6][2];
    #pragma unroll
    for (int j = 0; j < 6; j++)
        #pragma unroll
        for (int q = 0; q < 2; q++)
            wd2r[j][q] = *(const ulonglong2*)(Wd2t + 4 * lane + j * 256 + 128 * q);

    float nxt0 = 0.f, nxt1 = 0.f;
    if (ldp) { nxt0 = lsrc[base0]; nxt1 = lsrc[base1]; }

    for (int t = 0; t < T_; t++) {
        const float ld0 = nxt0, ld1 = nxt1;
        // prefetch next step's inputs
        {
            int tn = (t + 1 < T_) ? (t + 1) : (T_ - 1);
            if (ldp) { nxt0 = lsrc[base0 + tn * 6]; nxt1 = lsrc[base1 + tn * 6]; }
        }

        // init accumulators from precomputed constant part
        u64 u2[4][4][2];   // [row][q][pair]
        #pragma unroll
        for (int q = 0; q < 4; q++)
            #pragma unroll
            for (int r = 0; r < 4; r++) {
                ulonglong2 c = *(const ulonglong2*)(csw + (q * 4 + r) * 128);
                u2[r][q][0] = c.x; u2[r][q][1] = c.y;
            }

        // layer 1: 18 dynamic inputs x 512 hidden, packed f32x2, W1 shared by 4 rows
        #pragma unroll
        for (int k = 0; k < 18; k++) {
            u64 xd[4];
            if (k < 12) {
                xd[0] = dup2(__shfl_sync(0xffffffffu, ld0, k));
                xd[1] = dup2(__shfl_sync(0xffffffffu, ld0, 16 + k));
                xd[2] = dup2(__shfl_sync(0xffffffffu, ld1, k));
                xd[3] = dup2(__shfl_sync(0xffffffffu, ld1, 16 + k));
            } else {
                xd[0] = dup2(xi[0][k - 12]);
                xd[1] = dup2(xi[1][k - 12]);
                xd[2] = dup2(xi[2][k - 12]);
                xd[3] = dup2(xi[3][k - 12]);
            }
            #pragma unroll
            for (int q = 0; q < 4; q++) {
                ulonglong2 w = *(const ulonglong2*)(W1w + k * 512 + 128 * q);
                #pragma unroll
                for (int r = 0; r < 4; r++) {
                    u2[r][q][0] = ffma2(xd[r], w.x, u2[r][q][0]);
                    u2[r][q][1] = ffma2(xd[r], w.y, u2[r][q][1]);
                }
            }
        }

        // relu (per 32-bit half; 64-bit reg is just a pair, movs coalesce)
        #pragma unroll
        for (int q = 0; q < 4; q++)
            #pragma unroll
            for (int r = 0; r < 4; r++) {
                u2[r][q][0] = relu2(u2[r][q][0]);
                u2[r][q][1] = relu2(u2[r][q][1]);
            }

        // layer 2a: stress head (energy half, q=0,1)
        float sf[4];
        #pragma unroll
        for (int r = 0; r < 4; r++) {
            u64 s2 = 0ULL;
            #pragma unroll
            for (int q = 0; q < 2; q++) {
                s2 = ffma2(u2[r][q][0], wen2r[q].x, s2);
                s2 = ffma2(u2[r][q][1], wen2r[q].y, s2);
            }
            float2 v = unpk(s2);
            sf[r] = v.x + v.y;
        }

        // layer 2b: kinetics head (q=2,3)
        float p[4][6];
        #pragma unroll
        for (int j = 0; j < 6; j++)
            #pragma unroll
            for (int r = 0; r < 4; r++) {
                u64 a2 = 0ULL;
                #pragma unroll
                for (int q = 0; q < 2; q++) {
                    a2 = ffma2(u2[r][q + 2][0], wd2r[j][q].x, a2);
                    a2 = ffma2(u2[r][q + 2][1], wd2r[j][q].y, a2);
                }
                float2 v = unpk(a2);
                p[r][j] = v.x + v.y;
            }

        // butterfly reductions (results land in all lanes)
        #pragma unroll
        for (int off = 16; off; off >>= 1) {
            #pragma unroll
            for (int r = 0; r < 4; r++) {
                sf[r] += __shfl_xor_sync(0xffffffffu, sf[r], off);
                #pragma unroll
                for (int j = 0; j < 6; j++)
                    p[r][j] += __shfl_xor_sync(0xffffffffu, p[r][j], off);
            }
        }

        // outputs: stress[b,t] and xi BEFORE update
        if (lane == 0) {
            out[(row0 + 0) * T_ + t] = sf[0] + ben2r;
            float* xo = out + B_ * T_ + ((row0 + 0) * T_ + t) * 6;
            *(float2*)(xo)     = make_float2(xi[0][0], xi[0][1]);
            *(float2*)(xo + 2) = make_float2(xi[0][2], xi[0][3]);
            *(float2*)(xo + 4) = make_float2(xi[0][4], xi[0][5]);
        } else if (lane == 1) {
            out[(row0 + 1) * T_ + t] = sf[1] + ben2r;
            float* xo = out + B_ * T_ + ((row0 + 1) * T_ + t) * 6;
            *(float2*)(xo)     = make_float2(xi[1][0], xi[1][1]);
            *(float2*)(xo + 2) = make_float2(xi[1][2], xi[1][3]);
            *(float2*)(xo + 4) = make_float2(xi[1][4], xi[1][5]);
        } else if (lane == 2) {
            out[(row0 + 2) * T_ + t] = sf[2] + ben2r;
            float* xo = out + B_ * T_ + ((row0 + 2) * T_ + t) * 6;
            *(float2*)(xo)     = make_float2(xi[2][0], xi[2][1]);
            *(float2*)(xo + 2) = make_float2(xi[2][2], xi[2][3]);
            *(float2*)(xo + 4) = make_float2(xi[2][4], xi[2][5]);
        } else if (lane == 3) {
            out[(row0 + 3) * T_ + t] = sf[3] + ben2r;
            float* xo = out + B_ * T_ + ((row0 + 3) * T_ + t) * 6;
            *(float2*)(xo)     = make_float2(xi[3][0], xi[3][1]);
            *(float2*)(xo + 2) = make_float2(xi[3][2], xi[3][3]);
            *(float2*)(xo + 4) = make_float2(xi[3][4], xi[3][5]);
        }

        // explicit Euler update
        #pragma unroll
        for (int r = 0; r < 4; r++)
            #pragma unroll
            for (int j = 0; j < 6; j++)
                xi[r][j] = fmaf(DT_, p[r][j] + bd2r[j], xi[r][j]);
    }
}

extern "C" void kernel_launch(void* const* d_in, const int* in_sizes, int n_in,
                              void* d_out, int out_size) {
    (void)in_sizes; (void)n_in; (void)out_size;
    cudaFuncSetAttribute(visco_kernel,
                         cudaFuncAttributeMaxDynamicSharedMemorySize, SMEM_BYTES);
    visco_kernel<<<NBLK, THREADS, SMEM_BYTES>>>(
        (const float*)d_in[0],  (const float*)d_in[1],
        (const float*)d_in[2],  (const float*)d_in[3],
        (const float*)d_in[4],  (const float*)d_in[5],
        (const float*)d_in[6],  (const float*)d_in[7],
        (const float*)d_in[8],  (const float*)d_in[9],
        (const float*)d_in[10], (const float*)d_in[11],
        (const float*)d_in[12], (const float*)d_in[13],
        (const float*)d_in[14], (const float*)d_in[15],
        (float*)d_out);
}

// round 3
// speedup vs baseline: 1.7558x; 1.2342x over previous
#include <cuda_runtime.h>

#define B_ 8192
#define T_ 128
#define DT_ 0.01f
#define WARPS 4
#define THREADS 128
#define ROWS_PER_BLOCK 16
#define NBLK (B_ / ROWS_PER_BLOCK)

// shared memory layout (float offsets)
#define OFF_W1   0       // [18][512]
#define OFF_WEN2 9216    // [256]
#define OFF_WD2T 9472    // [6][256] (transposed Wd2)
#define OFF_CS   11008   // [4 warps][q=4][r=4][lane=32][4]
#define SMEM_FLOATS (11008 + WARPS * 2048)
#define SMEM_BYTES (SMEM_FLOATS * 4)

typedef unsigned long long u64;

__device__ __forceinline__ u64 ffma2(u64 a, u64 b, u64 c) {
    u64 d; asm("fma.rn.f32x2 %0, %1, %2, %3;" : "=l"(d) : "l"(a), "l"(b), "l"(c));
    return d;
}
__device__ __forceinline__ u64 dup2(float x) {
    u64 d; asm("mov.b64 %0, {%1, %1};" : "=l"(d) : "f"(x));
    return d;
}
__device__ __forceinline__ float2 unpk(u64 a) {
    float2 r; asm("mov.b64 {%0, %1}, %2;" : "=f"(r.x), "=f"(r.y) : "l"(a));
    return r;
}
__device__ __forceinline__ u64 pk2(float x, float y) {
    u64 d; asm("mov.b64 %0, {%1, %2};" : "=l"(d) : "f"(x), "f"(y));
    return d;
}
__device__ __forceinline__ u64 relu2(u64 a) {
    float2 v = unpk(a);
    return pk2(fmaxf(v.x, 0.f), fmaxf(v.y, 0.f));
}

__global__ void __launch_bounds__(THREADS, 2) visco_kernel(
    const float* __restrict__ e_,   const float* __restrict__ ed_,
    const float* __restrict__ E_,   const float* __restrict__ nu_,
    const float* __restrict__ We,   const float* __restrict__ be,
    const float* __restrict__ Wn,   const float* __restrict__ bn,
    const float* __restrict__ Wen1, const float* __restrict__ ben1,
    const float* __restrict__ Wen2, const float* __restrict__ ben2,
    const float* __restrict__ Wd1,  const float* __restrict__ bd1,
    const float* __restrict__ Wd2,  const float* __restrict__ bd2,
    float* __restrict__ out)
{
    extern __shared__ float sm[];
    float* W1s   = sm + OFF_W1;
    float* Wen2s = sm + OFF_WEN2;
    float* Wd2t  = sm + OFF_WD2T;
    float* cs    = sm + OFF_CS;

    const int tid  = threadIdx.x;
    const int lane = tid & 31;
    const int warp = tid >> 5;

    // ---- cooperative smem fill ----
    for (int i = tid; i < 18 * 512; i += THREADS) {
        int k = i >> 9, h = i & 511;
        W1s[i] = (h < 256) ? Wen1[k * 256 + h] : Wd1[k * 256 + (h - 256)];
    }
    for (int i = tid; i < 256; i += THREADS) Wen2s[i] = Wen2[i];
    for (int i = tid; i < 6 * 256; i += THREADS) {
        int j = i >> 8, h = i & 255;
        Wd2t[i] = Wd2[h * 6 + j];   // transpose -> conflict-free float4 reads
    }

    const int gw   = blockIdx.x * WARPS + warp;
    const int row0 = gw * 4;

    // ---- precompute per-row constant part: c[h] = b1[h] + mf(32) @ W1[18:50][h] ----
    {
        float Er[4], nur[4];
        #pragma unroll
        for (int r = 0; r < 4; r++) { Er[r] = E_[row0 + r]; nur[r] = nu_[row0 + r]; }
        #pragma unroll
        for (int q = 0; q < 4; q++) {
            const int h0 = 4 * lane + 128 * q;   // whole float4 lies in one half
            const float* bsrc  = (h0 < 256) ? (ben1 + h0) : (bd1 + h0 - 256);
            const float* Wbase = (h0 < 256) ? (Wen1 + 18 * 256 + h0)
                                            : (Wd1  + 18 * 256 + h0 - 256);
            float c[4][4];  // [el][row]
            #pragma unroll
            for (int el = 0; el < 4; el++) {
                float b = bsrc[el];
                #pragma unroll
                for (int r = 0; r < 4; r++) c[el][r] = b;
            }
            for (int k = 0; k < 32; k++) {
                float w, b;
                if (k < 16) { w = We[k];      b = be[k]; }
                else        { w = Wn[k - 16]; b = bn[k - 16]; }
                float4 w4 = *(const float4*)(Wbase + k * 256);
                #pragma unroll
                for (int r = 0; r < 4; r++) {
                    float m = fmaf((k < 16) ? Er[r] : nur[r], w, b);
                    c[0][r] = fmaf(m, w4.x, c[0][r]);
                    c[1][r] = fmaf(m, w4.y, c[1][r]);
                    c[2][r] = fmaf(m, w4.z, c[2][r]);
                    c[3][r] = fmaf(m, w4.w, c[3][r]);
                }
            }
            #pragma unroll
            for (int r = 0; r < 4; r++) {
                *(float4*)(cs + warp * 2048 + ((q * 4 + r) * 32 + lane) * 4)
                    = make_float4(c[0][r], c[1][r], c[2][r], c[3][r]);
            }
        }
    }
    __syncthreads();

    // ---- distributed state: lane i = r*8+j owns output slot (r, j) ----
    // j in [0,6): xi component j of row r.  j == 6: stress of row r.  j == 7: dummy.
    const int jown = lane & 7;
    const int rown = lane >> 3;
    const float bd2v  = (jown < 6) ? bd2[jown] : 0.f;
    const float ben2r = ben2[0];
    float xi_val = 0.f;

    // per-slot output pointers (computed once)
    float* xi_ptr = out + B_ * T_ + ((row0 + rown) * T_) * 6 + jown;   // + t*6
    float* s_ptr  = out + (row0 + rown) * T_;                          // + t

    // lane -> (rowpair, input-dim) mapping for the per-step e/edot gather
    const int l2  = lane & 15;
    const bool ldp = (l2 < 12);
    const float* lsrc = (l2 < 6) ? e_ : ed_;
    const int d_l = (l2 < 6) ? l2 : (l2 - 6);
    const int rA = row0 + ((lane < 16) ? 0 : 1);   // source rows for ld0
    const int rB = row0 + ((lane < 16) ? 2 : 3);   // source rows for ld1
    const int base0 = rA * T_ * 6 + d_l;
    const int base1 = rB * T_ * 6 + d_l;

    const float* W1w = W1s + 4 * lane;                 // + k*512 + 128*q
    const float* csw = cs + warp * 2048 + 4 * lane;    // + (q*4+r)*128

    // hoist layer-2 weights into registers (loop-invariant)
    ulonglong2 wen2r[2];
    #pragma unroll
    for (int q = 0; q < 2; q++)
        wen2r[q] = *(const ulonglong2*)(Wen2s + 4 * lane + 128 * q);
    ulonglong2 wd2r[6][2];
    #pragma unroll
    for (int j = 0; j < 6; j++)
        #pragma unroll
        for (int q = 0; q < 2; q++)
            wd2r[j][q] = *(const ulonglong2*)(Wd2t + 4 * lane + j * 256 + 128 * q);

    float nxt0 = 0.f, nxt1 = 0.f;
    if (ldp) { nxt0 = lsrc[base0]; nxt1 = lsrc[base1]; }

    for (int t = 0; t < T_; t++) {
        const float ld0 = nxt0, ld1 = nxt1;
        {
            int tn = (t + 1 < T_) ? (t + 1) : (T_ - 1);
            if (ldp) { nxt0 = lsrc[base0 + tn * 6]; nxt1 = lsrc[base1 + tn * 6]; }
        }

        // init accumulators from precomputed constant part
        u64 u2[4][4][2];   // [row][q][pair]
        #pragma unroll
        for (int q = 0; q < 4; q++)
            #pragma unroll
            for (int r = 0; r < 4; r++) {
                ulonglong2 c = *(const ulonglong2*)(csw + (q * 4 + r) * 128);
                u2[r][q][0] = c.x; u2[r][q][1] = c.y;
            }

        // layer 1: 18 dynamic inputs x 512 hidden, packed f32x2, W1 shared by 4 rows
        #pragma unroll
        for (int k = 0; k < 18; k++) {
            u64 xd[4];
            if (k < 12) {
                xd[0] = dup2(__shfl_sync(0xffffffffu, ld0, k));
                xd[1] = dup2(__shfl_sync(0xffffffffu, ld0, 16 + k));
                xd[2] = dup2(__shfl_sync(0xffffffffu, ld1, k));
                xd[3] = dup2(__shfl_sync(0xffffffffu, ld1, 16 + k));
            } else {
                // xi[r][k-12] lives in lane r*8 + (k-12)
                const int js = k - 12;
                xd[0] = dup2(__shfl_sync(0xffffffffu, xi_val, 0 * 8 + js));
                xd[1] = dup2(__shfl_sync(0xffffffffu, xi_val, 1 * 8 + js));
                xd[2] = dup2(__shfl_sync(0xffffffffu, xi_val, 2 * 8 + js));
                xd[3] = dup2(__shfl_sync(0xffffffffu, xi_val, 3 * 8 + js));
            }
            #pragma unroll
            for (int q = 0; q < 4; q++) {
                ulonglong2 w = *(const ulonglong2*)(W1w + k * 512 + 128 * q);
                #pragma unroll
                for (int r = 0; r < 4; r++) {
                    u2[r][q][0] = ffma2(xd[r], w.x, u2[r][q][0]);
                    u2[r][q][1] = ffma2(xd[r], w.y, u2[r][q][1]);
                }
            }
        }

        // relu
        #pragma unroll
        for (int q = 0; q < 4; q++)
            #pragma unroll
            for (int r = 0; r < 4; r++) {
                u2[r][q][0] = relu2(u2[r][q][0]);
                u2[r][q][1] = relu2(u2[r][q][1]);
            }

        // layer-2 local partials into slot array v[32]; slot i = r*8+j
        float v[32];
        #pragma unroll
        for (int r = 0; r < 4; r++) {
            // kinetics (q=2,3)
            #pragma unroll
            for (int j = 0; j < 6; j++) {
                u64 a2 = 0ULL;
                #pragma unroll
                for (int q = 0; q < 2; q++) {
                    a2 = ffma2(u2[r][q + 2][0], wd2r[j][q].x, a2);
                    a2 = ffma2(u2[r][q + 2][1], wd2r[j][q].y, a2);
                }
                float2 w = unpk(a2);
                v[r * 8 + j] = w.x + w.y;
            }
            // stress (q=0,1)
            {
                u64 s2 = 0ULL;
                #pragma unroll
                for (int q = 0; q < 2; q++) {
                    s2 = ffma2(u2[r][q][0], wen2r[q].x, s2);
                    s2 = ffma2(u2[r][q][1], wen2r[q].y, s2);
                }
                float2 w = unpk(s2);
                v[r * 8 + 6] = w.x + w.y;
            }
            v[r * 8 + 7] = 0.f;
        }

        // fold-distribute reduction: lane i ends with sum over lanes of v[i]
        #pragma unroll
        for (int lvl = 0; lvl < 5; lvl++) {
            const int off = 16 >> lvl;      // also the half-size at this level
            #pragma unroll
            for (int m = 0; m < (16 >> lvl); m++) {
                float send = (lane & off) ? v[m] : v[m + off];
                float recv = __shfl_xor_sync(0xffffffffu, send, off);
                float keep = (lane & off) ? v[m + off] : v[m];
                v[m] = keep + recv;
            }
        }
        // v[0] now holds this lane's owned slot value

        // outputs: xi BEFORE update (owner lanes j<6), stress (j==6)
        if (jown < 6)       xi_ptr[t * 6] = xi_val;
        else if (jown == 6) s_ptr[t] = v[0] + ben2r;

        // explicit Euler update (garbage on non-owner lanes, never read)
        xi_val = fmaf(DT_, v[0] + bd2v, xi_val);
    }
}

extern "C" void kernel_launch(void* const* d_in, const int* in_sizes, int n_in,
                              void* d_out, int out_size) {
    (void)in_sizes; (void)n_in; (void)out_size;
    cudaFuncSetAttribute(visco_kernel,
                         cudaFuncAttributeMaxDynamicSharedMemorySize, SMEM_BYTES);
    visco_kernel<<<NBLK, THREADS, SMEM_BYTES>>>(
        (const float*)d_in[0],  (const float*)d_in[1],
        (const float*)d_in[2],  (const float*)d_in[3],
        (const float*)d_in[4],  (const float*)d_in[5],
        (const float*)d_in[6],  (const float*)d_in[7],
        (const float*)d_in[8],  (const float*)d_in[9],
        (const float*)d_in[10], (const float*)d_in[11],
        (const float*)d_in[12], (const float*)d_in[13],
        (const float*)d_in[14], (const float*)d_in[15],
        (float*)d_out);
}